// round 1
// baseline (speedup 1.0000x reference)
#include <cuda_runtime.h>
#include <math.h>

// ============================================================================
// TPForth: e3nn-style tensor product, B x (x1[156], x2[9], w[7128]) -> out[156]
// HBM-bound streaming kernel: one 256-thread block per batch row.
// ============================================================================

#define WTOT 7128
#define XW   156

// Weight sub-matrix offsets (floats within a row), shapes (U, Wd):
//  w00  @    0 (48,48)   w01  @ 2304 (48,10)   w10  @ 2784 (10,10)
//  w110 @ 2884 (10,48)   w112 @ 3364 (10,10)   w12  @ 3464 (10,10)
//  w20  @ 3564 (10,10)   w211 @ 3664 (10,10)   w213 @ 3764 (10,48)
//  w22  @ 4244 (10,10)   w30  @ 4344 (48,48)   w31  @ 6648 (48,10)

__device__ float d_w3j111[27];   // wigner_3j(1,1,1), shape (3,3,3)
__device__ float d_w3j121[45];   // wigner_3j(1,2,1), shape (3,5,3)

// ---------------------------------------------------------------------------
// Device-side exact replication of the reference Wigner-3j construction (fp64)
// ---------------------------------------------------------------------------
struct C2 { double r, i; };
__device__ __forceinline__ C2 cmul(C2 a, C2 b) {
    C2 c; c.r = a.r*b.r - a.i*b.i; c.i = a.r*b.i + a.i*b.r; return c;
}
__device__ double dfact(int n) {
    double r = 1.0; for (int k = 2; k <= n; k++) r *= (double)k; return r;
}

__device__ void change_basis(int l, C2* q) {  // q[(2l+1)*(2l+1)], row-major
    int n = 2*l + 1;
    for (int a = 0; a < n*n; a++) { q[a].r = 0.0; q[a].i = 0.0; }
    double rs2 = 1.0 / sqrt(2.0);
    for (int m = -l; m < 0; m++) {
        q[(l+m)*n + (l - m)].r =  rs2;   // col l+|m|
        q[(l+m)*n + (l + m)].i = -rs2;   // col l-|m|
    }
    q[l*n + l].r = 1.0;
    for (int m = 1; m <= l; m++) {
        double s = (m & 1) ? -1.0 : 1.0;
        q[(l+m)*n + (l+m)].r = s * rs2;
        q[(l+m)*n + (l-m)].i = s * rs2;
    }
    C2 ph;
    switch (l & 3) {  // (-i)^l
        case 0: ph.r = 1;  ph.i = 0;  break;
        case 1: ph.r = 0;  ph.i = -1; break;
        case 2: ph.r = -1; ph.i = 0;  break;
        default: ph.r = 0; ph.i = 1;  break;
    }
    for (int a = 0; a < n*n; a++) q[a] = cmul(q[a], ph);
}

__device__ double cg_coeff(int j1, int j2, int j3, int m1, int m2, int m3) {
    int vmin = -j1 + j2 + m3;
    if (-j1 + m1 > vmin) vmin = -j1 + m1;
    if (0 > vmin) vmin = 0;
    int vmax = j2 + j3 + m1;
    if (j3 - j1 + j2 < vmax) vmax = j3 - j1 + j2;
    if (j3 + m3 < vmax) vmax = j3 + m3;
    double C = sqrt((2.0*j3 + 1.0) * dfact(j3+j1-j2) * dfact(j3-j1+j2) * dfact(j1+j2-j3)
                    * dfact(j3+m3) * dfact(j3-m3)
                    / (dfact(j1+j2+j3+1) * dfact(j1-m1) * dfact(j1+m1)
                       * dfact(j2-m2) * dfact(j2+m2)));
    double S = 0.0;
    for (int v = vmin; v <= vmax; v++) {
        double sgn = ((v + j2 + m2) & 1) ? -1.0 : 1.0;
        S += sgn * dfact(j2+j3+m1-v) * dfact(j1-m1+v)
             / (dfact(v) * dfact(j3-j1+j2-v) * dfact(j3+m3-v) * dfact(v+j1-j2-m3));
    }
    return C * S;
}

__device__ void compute_w3j(int l1, int l2, int l3, float* out) {
    int n1 = 2*l1+1, n2 = 2*l2+1, n3 = 2*l3+1;
    C2 Q1[25], Q2[25], Q3[25];
    change_basis(l1, Q1); change_basis(l2, Q2); change_basis(l3, Q3);
    double cg[5][5][5];
    for (int a = 0; a < 5; a++) for (int b = 0; b < 5; b++) for (int c = 0; c < 5; c++)
        cg[a][b][c] = 0.0;
    for (int i1 = 0; i1 < n1; i1++) for (int i2 = 0; i2 < n2; i2++) {
        int m1 = i1 - l1, m2 = i2 - l2, m3 = m1 + m2;
        if (m3 >= -l3 && m3 <= l3)
            cg[i1][i2][l3 + m3] = cg_coeff(l1, l2, l3, m1, m2, m3);
    }
    double Cr[125];
    double norm2 = 0.0;
    for (int j = 0; j < n1; j++) for (int l = 0; l < n2; l++) for (int m = 0; m < n3; m++) {
        C2 acc; acc.r = 0.0; acc.i = 0.0;
        for (int i = 0; i < n1; i++) for (int k = 0; k < n2; k++) for (int nn = 0; nn < n3; nn++) {
            double cgv = cg[i][k][nn];
            if (cgv == 0.0) continue;
            C2 t = cmul(Q1[i*n1 + j], Q2[k*n2 + l]);
            C2 q3c; q3c.r = Q3[nn*n3 + m].r; q3c.i = -Q3[nn*n3 + m].i;  // conj(Q3.T)[m,nn]
            t = cmul(t, q3c);
            acc.r += t.r * cgv; acc.i += t.i * cgv;
        }
        Cr[(j*n2 + l)*n3 + m] = acc.r;
        norm2 += acc.r * acc.r;
    }
    double inv = 1.0 / sqrt(norm2);
    for (int a = 0; a < n1*n2*n3; a++) out[a] = (float)(Cr[a] * inv);
}

__global__ void init_w3j_kernel() {
    if (threadIdx.x == 0) {
        compute_w3j(1, 1, 1, d_w3j111);
        compute_w3j(1, 2, 1, d_w3j121);
    }
}

// ---------------------------------------------------------------------------
// Main kernel: one block per batch row.
// ---------------------------------------------------------------------------
__global__ __launch_bounds__(256) void tp_kernel(
    const float* __restrict__ x1,
    const float* __restrict__ x2,
    const float* __restrict__ w,
    float* __restrict__ out)
{
    __shared__ __align__(16) float sw[WTOT];
    __shared__ __align__(16) float sx1[XW];
    __shared__ float sx2[9];
    __shared__ float s_d110[10], s_d213[10];
    __shared__ float s_c112[30], s_c12[30], s_c211[30], s_c22[30];
    __shared__ float sj1[27], sj2[45];

    const int z   = blockIdx.x;
    const int tid = threadIdx.x;

    // ---- Stage: fully-coalesced float4 loads of this row's weights ----
    const float4* __restrict__ ws4 = reinterpret_cast<const float4*>(w) + (size_t)z * (WTOT/4);
    float4* sw4 = reinterpret_cast<float4*>(sw);
    #pragma unroll
    for (int i = 0; i < 7; i++) {
        int idx = tid + i * 256;
        if (idx < WTOT/4) sw4[idx] = ws4[idx];
    }
    if (tid < XW/4)
        reinterpret_cast<float4*>(sx1)[tid] =
            (reinterpret_cast<const float4*>(x1) + (size_t)z * (XW/4))[tid];
    if (tid >= 64 && tid < 73)   sx2[tid - 64]  = x2[(size_t)z * 9 + (tid - 64)];
    if (tid >= 96 && tid < 123)  sj1[tid - 96]  = d_w3j111[tid - 96];
    if (tid >= 128 && tid < 173) sj2[tid - 128] = d_w3j121[tid - 128];
    __syncthreads();

    // ---- Aux: per-u contraction coefficients (a-vectors) ----
    if (tid < 10) {
        float s = 0.f;
        #pragma unroll
        for (int i = 0; i < 3; i++) s += sx1[48 + tid*3 + i] * sx2[1 + i];
        s_d110[tid] = s;                                 // x1_1o . x2_1o
    } else if (tid < 20) {
        int u = tid - 10; float s = 0.f;
        #pragma unroll
        for (int i = 0; i < 3; i++) s += sx1[78 + u*3 + i] * sx2[1 + i];
        s_d213[u] = s;                                   // x1_1e . x2_1o
    } else if (tid < 50) {
        int t = tid - 20, u = t/3, k = t%3; float s = 0.f;
        #pragma unroll
        for (int i = 0; i < 3; i++)
            #pragma unroll
            for (int j = 0; j < 3; j++)
                s += sx1[48 + u*3 + i] * sx2[1 + j] * sj1[i*9 + j*3 + k];
        s_c112[t] = s;                                   // (x1_1o x x2_1o) via w3j111
    } else if (tid < 80) {
        int t = tid - 50, u = t/3, k = t%3; float s = 0.f;
        #pragma unroll
        for (int i = 0; i < 3; i++)
            #pragma unroll
            for (int j = 0; j < 5; j++)
                s += sx1[48 + u*3 + i] * sx2[4 + j] * sj2[i*15 + j*3 + k];
        s_c12[t] = s;                                    // x1_1o (x) x2_2e via w3j121
    } else if (tid < 110) {
        int t = tid - 80, u = t/3, k = t%3; float s = 0.f;
        #pragma unroll
        for (int i = 0; i < 3; i++)
            #pragma unroll
            for (int j = 0; j < 3; j++)
                s += sx1[78 + u*3 + i] * sx2[1 + j] * sj1[i*9 + j*3 + k];
        s_c211[t] = s;                                   // x1_1e (x) x2_1o via w3j111
    } else if (tid < 140) {
        int t = tid - 110, u = t/3, k = t%3; float s = 0.f;
        #pragma unroll
        for (int i = 0; i < 3; i++)
            #pragma unroll
            for (int j = 0; j < 5; j++)
                s += sx1[78 + u*3 + i] * sx2[4 + j] * sj2[i*15 + j*3 + k];
        s_c22[t] = s;                                    // x1_1e (x) x2_2e via w3j121
    }
    __syncthreads();

    // ---- Main: one thread per output element ----
    const float NORM_0E = 0.13130643285972254f;  // sqrt(1/58)
    const float NORM_1O = 0.19611613513818404f;  // sqrt(3/78)
    const float NORM_1E = 0.19611613513818404f;  // sqrt(3/78)
    const float NORM_0O = 0.13130643285972254f;  // sqrt(1/58)
    const float RS3     = 0.57735026918962576f;  // 1/sqrt(3)

    float* orow = out + (size_t)z * XW;

    if (tid < 48) {
        // r0e[w] = N0E*( x2_0e * sum_u x1_0e[u] W00[u,w] + RS3 * sum_u d110[u] W110[u,w] )
        int wI = tid;
        float a = 0.f;
        #pragma unroll 8
        for (int u = 0; u < 48; u++) a += sx1[u] * sw[0 + u*48 + wI];
        float b = 0.f;
        #pragma unroll
        for (int u = 0; u < 10; u++) b += s_d110[u] * sw[2884 + u*48 + wI];
        orow[wI] = NORM_0E * (a * sx2[0] + RS3 * b);
    } else if (tid < 78) {
        // r1o[w,i]
        int t = tid - 48, wI = t/3, i = t%3;
        float t01 = 0.f;
        #pragma unroll 8
        for (int u = 0; u < 48; u++) t01 += sx1[u] * sw[2304 + u*10 + wI];
        float a10 = 0.f, a12 = 0.f, a211 = 0.f;
        #pragma unroll
        for (int u = 0; u < 10; u++) {
            a10  += sx1[48 + u*3 + i] * sw[2784 + u*10 + wI];
            a12  += s_c12[u*3 + i]    * sw[3464 + u*10 + wI];
            a211 += s_c211[u*3 + i]   * sw[3664 + u*10 + wI];
        }
        orow[48 + wI*3 + i] =
            NORM_1O * (RS3 * (t01 * sx2[1 + i] + sx2[0] * a10) + a12 + a211);
    } else if (tid < 108) {
        // r1e[w,k]
        int t = tid - 78, wI = t/3, k = t%3;
        float t31 = 0.f;
        #pragma unroll 8
        for (int u = 0; u < 48; u++) t31 += sx1[108 + u] * sw[6648 + u*10 + wI];
        float a112 = 0.f, a20 = 0.f, a22 = 0.f;
        #pragma unroll
        for (int u = 0; u < 10; u++) {
            a112 += s_c112[u*3 + k]   * sw[3364 + u*10 + wI];
            a20  += sx1[78 + u*3 + k] * sw[3564 + u*10 + wI];
            a22  += s_c22[u*3 + k]    * sw[4244 + u*10 + wI];
        }
        orow[78 + wI*3 + k] =
            NORM_1E * (a112 + RS3 * (sx2[0] * a20 + t31 * sx2[1 + k]) + a22);
    } else if (tid < 156) {
        // r0o[w] = N0O*( RS3 * sum_u d213[u] W213[u,w] + x2_0e * sum_u x1_0o[u] W30[u,w] )
        int wI = tid - 108;
        float a = 0.f;
        #pragma unroll
        for (int u = 0; u < 10; u++) a += s_d213[u] * sw[3764 + u*48 + wI];
        float b = 0.f;
        #pragma unroll 8
        for (int u = 0; u < 48; u++) b += sx1[108 + u] * sw[4344 + u*48 + wI];
        orow[108 + wI] = NORM_0O * (RS3 * a + b * sx2[0]);
    }
}

// ---------------------------------------------------------------------------
extern "C" void kernel_launch(void* const* d_in, const int* in_sizes, int n_in,
                              void* d_out, int out_size)
{
    const float* x1 = (const float*)d_in[0];
    const float* x2 = (const float*)d_in[1];
    const float* w  = (const float*)d_in[2];
    float* out = (float*)d_out;

    int B = in_sizes[1] / 9;   // x2 has 9 floats per row

    init_w3j_kernel<<<1, 32>>>();
    tp_kernel<<<B, 256>>>(x1, x2, w, out);
}

// round 2
// speedup vs baseline: 4.9736x; 4.9736x over previous
#include <cuda_runtime.h>
#include <math.h>
#include <stdint.h>

// ============================================================================
// TPForth: e3nn-style tensor product, B x (x1[156], x2[9], w[7128]) -> out[156]
// HBM-bound streaming kernel: one 160-thread block per batch row.
// Weights staged to smem via cp.async.bulk (bypasses L1 reg round-trip).
// ============================================================================

#define WTOT 7128
#define WBYTES (WTOT * 4)
#define XW   156

// Weight sub-matrix offsets (floats within a row), shapes (U, Wd):
//  w00  @    0 (48,48)   w01  @ 2304 (48,10)   w10  @ 2784 (10,10)
//  w110 @ 2884 (10,48)   w112 @ 3364 (10,10)   w12  @ 3464 (10,10)
//  w20  @ 3564 (10,10)   w211 @ 3664 (10,10)   w213 @ 3764 (10,48)
//  w22  @ 4244 (10,10)   w30  @ 4344 (48,48)   w31  @ 6648 (48,10)

__device__ float d_w3j111[27];   // wigner_3j(1,1,1), shape (3,3,3)
__device__ float d_w3j121[45];   // wigner_3j(1,2,1), shape (3,5,3)

// ---------------------------------------------------------------------------
// Parallel fp32 Wigner-3j init: one tensor element per thread.
// ---------------------------------------------------------------------------
struct CF { float r, i; };
__device__ __forceinline__ CF cmulf(CF a, CF b) {
    CF c; c.r = a.r*b.r - a.i*b.i; c.i = a.r*b.i + a.i*b.r; return c;
}

__device__ void change_basis_f(int l, CF* q) {  // q[(2l+1)^2], row-major
    int n = 2*l + 1;
    for (int a = 0; a < n*n; a++) { q[a].r = 0.f; q[a].i = 0.f; }
    const float rs2 = 0.70710678118654752f;
    for (int m = -l; m < 0; m++) {
        q[(l+m)*n + (l - m)].r =  rs2;
        q[(l+m)*n + (l + m)].i = -rs2;
    }
    q[l*n + l].r = 1.f;
    for (int m = 1; m <= l; m++) {
        float s = (m & 1) ? -1.f : 1.f;
        q[(l+m)*n + (l+m)].r = s * rs2;
        q[(l+m)*n + (l-m)].i = s * rs2;
    }
    CF ph;
    switch (l & 3) {  // (-i)^l
        case 0: ph.r = 1;  ph.i = 0;  break;
        case 1: ph.r = 0;  ph.i = -1; break;
        case 2: ph.r = -1; ph.i = 0;  break;
        default: ph.r = 0; ph.i = 1;  break;
    }
    for (int a = 0; a < n*n; a++) q[a] = cmulf(q[a], ph);
}

__device__ float cg_f(int j1, int j2, int j3, int m1, int m2, int m3,
                      const float* ft) {
    int vmin = -j1 + j2 + m3;
    if (-j1 + m1 > vmin) vmin = -j1 + m1;
    if (0 > vmin) vmin = 0;
    int vmax = j2 + j3 + m1;
    if (j3 - j1 + j2 < vmax) vmax = j3 - j1 + j2;
    if (j3 + m3 < vmax) vmax = j3 + m3;
    float C = sqrtf((2.f*j3 + 1.f) * ft[j3+j1-j2] * ft[j3-j1+j2] * ft[j1+j2-j3]
                    * ft[j3+m3] * ft[j3-m3]
                    / (ft[j1+j2+j3+1] * ft[j1-m1] * ft[j1+m1]
                       * ft[j2-m2] * ft[j2+m2]));
    float S = 0.f;
    for (int v = vmin; v <= vmax; v++) {
        float sgn = ((v + j2 + m2) & 1) ? -1.f : 1.f;
        S += sgn * ft[j2+j3+m1-v] * ft[j1-m1+v]
             / (ft[v] * ft[j3-j1+j2-v] * ft[j3+m3-v] * ft[v+j1-j2-m3]);
    }
    return C * S;
}

// Unnormalized element C[j,l,m] of wigner_3j(l1,l2,l3)
__device__ float w3j_elem(int l1, int l2, int l3, int j, int l, int m,
                          const float* ft) {
    int n1 = 2*l1+1, n2 = 2*l2+1, n3 = 2*l3+1;
    CF Q1[25], Q2[25], Q3[25];
    change_basis_f(l1, Q1);
    change_basis_f(l2, Q2);
    change_basis_f(l3, Q3);
    float acc = 0.f;
    for (int i = 0; i < n1; i++) {
        for (int k = 0; k < n2; k++) {
            int m3v = (i - l1) + (k - l2);
            if (m3v < -l3 || m3v > l3) continue;
            int nn = l3 + m3v;
            float cgv = cg_f(l1, l2, l3, i - l1, k - l2, m3v, ft);
            CF t = cmulf(Q1[i*n1 + j], Q2[k*n2 + l]);
            CF q3c; q3c.r = Q3[nn*n3 + m].r; q3c.i = -Q3[nn*n3 + m].i;
            t = cmulf(t, q3c);
            acc += t.r * cgv;
        }
    }
    return acc;
}

__global__ void init_w3j_kernel() {
    __shared__ float s111[27], s121[45];
    __shared__ float inv111, inv121;
    int tid = threadIdx.x;
    float ft[8];
    ft[0] = 1.f;
    for (int k = 1; k < 8; k++) ft[k] = ft[k-1] * (float)k;

    if (tid < 27) {
        int j = tid / 9, rem = tid % 9, l = rem / 3, m = rem % 3;
        s111[tid] = w3j_elem(1, 1, 1, j, l, m, ft);
    } else if (tid >= 32 && tid < 77) {
        int idx = tid - 32;
        int j = idx / 15, rem = idx % 15, l = rem / 3, m = rem % 3;
        s121[idx] = w3j_elem(1, 2, 1, j, l, m, ft);
    }
    __syncthreads();
    if (tid == 0) {
        float s = 0.f;
        for (int a = 0; a < 27; a++) s += s111[a] * s111[a];
        inv111 = rsqrtf(s);
    }
    if (tid == 1) {
        float s = 0.f;
        for (int a = 0; a < 45; a++) s += s121[a] * s121[a];
        inv121 = rsqrtf(s);
    }
    __syncthreads();
    if (tid < 27) d_w3j111[tid] = s111[tid] * inv111;
    if (tid >= 32 && tid < 77) d_w3j121[tid - 32] = s121[tid - 32] * inv121;
}

// ---------------------------------------------------------------------------
// Main kernel: one block (160 threads) per batch row.
// ---------------------------------------------------------------------------
__device__ __forceinline__ uint32_t smem_u32(const void* p) {
    uint32_t a;
    asm("{ .reg .u64 t; cvta.to.shared.u64 t, %1; cvt.u32.u64 %0, t; }"
        : "=r"(a) : "l"(p));
    return a;
}

__global__ __launch_bounds__(160) void tp_kernel(
    const float* __restrict__ x1,
    const float* __restrict__ x2,
    const float* __restrict__ w,
    float* __restrict__ out)
{
    __shared__ __align__(16) float sw[WTOT];
    __shared__ __align__(16) float sx1[XW];
    __shared__ float sx2[9];
    __shared__ float s_d110[10], s_d213[10];
    __shared__ float s_c112[30], s_c12[30], s_c211[30], s_c22[30];
    __shared__ float sj1[27], sj2[45];
    __shared__ __align__(8) uint64_t mbar;

    const int z   = blockIdx.x;
    const int tid = threadIdx.x;

    const uint32_t mbar_a = smem_u32(&mbar);

    if (tid == 0) {
        asm volatile("mbarrier.init.shared.b64 [%0], %1;"
                     :: "r"(mbar_a), "r"(1) : "memory");
    }

    // ---- Small operand loads (overlap with bulk copy issue) ----
    if (tid < XW/4)
        reinterpret_cast<float4*>(sx1)[tid] =
            (reinterpret_cast<const float4*>(x1) + (size_t)z * (XW/4))[tid];
    else if (tid < 48)  sx2[tid - 39] = x2[(size_t)z * 9 + (tid - 39)];
    else if (tid < 75)  sj1[tid - 48] = d_w3j111[tid - 48];
    else if (tid < 120) sj2[tid - 75] = d_w3j121[tid - 75];
    __syncthreads();   // mbar init visible; sx1/sx2/sj ready

    // ---- Bulk async copy of this row's 28512B of weights ----
    if (tid == 0) {
        asm volatile("mbarrier.arrive.expect_tx.shared.b64 _, [%0], %1;"
                     :: "r"(mbar_a), "r"((uint32_t)WBYTES) : "memory");
        const float* src = w + (size_t)z * WTOT;
        asm volatile(
            "cp.async.bulk.shared::cluster.global.mbarrier::complete_tx::bytes "
            "[%0], [%1], %2, [%3];"
            :: "r"(smem_u32(sw)), "l"(src), "r"((uint32_t)WBYTES), "r"(mbar_a)
            : "memory");
    }

    // ---- Aux: per-u contraction coefficients (overlaps the bulk copy) ----
    if (tid < 10) {
        float s = 0.f;
        #pragma unroll
        for (int i = 0; i < 3; i++) s += sx1[48 + tid*3 + i] * sx2[1 + i];
        s_d110[tid] = s;                                 // x1_1o . x2_1o
    } else if (tid < 20) {
        int u = tid - 10; float s = 0.f;
        #pragma unroll
        for (int i = 0; i < 3; i++) s += sx1[78 + u*3 + i] * sx2[1 + i];
        s_d213[u] = s;                                   // x1_1e . x2_1o
    } else if (tid < 50) {
        int t = tid - 20, u = t/3, k = t%3; float s = 0.f;
        #pragma unroll
        for (int i = 0; i < 3; i++)
            #pragma unroll
            for (int j = 0; j < 3; j++)
                s += sx1[48 + u*3 + i] * sx2[1 + j] * sj1[i*9 + j*3 + k];
        s_c112[t] = s;                                   // x1_1o (x) x2_1o via w3j111
    } else if (tid < 80) {
        int t = tid - 50, u = t/3, k = t%3; float s = 0.f;
        #pragma unroll
        for (int i = 0; i < 3; i++)
            #pragma unroll
            for (int j = 0; j < 5; j++)
                s += sx1[48 + u*3 + i] * sx2[4 + j] * sj2[i*15 + j*3 + k];
        s_c12[t] = s;                                    // x1_1o (x) x2_2e via w3j121
    } else if (tid < 110) {
        int t = tid - 80, u = t/3, k = t%3; float s = 0.f;
        #pragma unroll
        for (int i = 0; i < 3; i++)
            #pragma unroll
            for (int j = 0; j < 3; j++)
                s += sx1[78 + u*3 + i] * sx2[1 + j] * sj1[i*9 + j*3 + k];
        s_c211[t] = s;                                   // x1_1e (x) x2_1o via w3j111
    } else if (tid < 140) {
        int t = tid - 110, u = t/3, k = t%3; float s = 0.f;
        #pragma unroll
        for (int i = 0; i < 3; i++)
            #pragma unroll
            for (int j = 0; j < 5; j++)
                s += sx1[78 + u*3 + i] * sx2[4 + j] * sj2[i*15 + j*3 + k];
        s_c22[t] = s;                                    // x1_1e (x) x2_2e via w3j121
    }
    __syncthreads();   // aux ready

    // ---- Wait for weights ----
    {
        uint32_t done;
        asm volatile(
            "{\n .reg .pred p;\n"
            " mbarrier.try_wait.parity.acquire.cta.shared::cta.b64 p, [%1], %2, 0x989680;\n"
            " selp.b32 %0, 1, 0, p;\n}"
            : "=r"(done) : "r"(mbar_a), "r"(0u) : "memory");
        while (!done) {
            asm volatile(
                "{\n .reg .pred p;\n"
                " mbarrier.try_wait.parity.acquire.cta.shared::cta.b64 p, [%1], %2, 0x989680;\n"
                " selp.b32 %0, 1, 0, p;\n}"
                : "=r"(done) : "r"(mbar_a), "r"(0u) : "memory");
        }
    }

    // ---- Main: one thread per output element ----
    const float NORM_0E = 0.13130643285972254f;  // sqrt(1/58)
    const float NORM_1O = 0.19611613513818404f;  // sqrt(3/78)
    const float NORM_1E = 0.19611613513818404f;  // sqrt(3/78)
    const float NORM_0O = 0.13130643285972254f;  // sqrt(1/58)
    const float RS3     = 0.57735026918962576f;  // 1/sqrt(3)

    float* orow = out + (size_t)z * XW;

    if (tid < 48) {
        // r0e[w]
        int wI = tid;
        float a = 0.f;
        #pragma unroll 8
        for (int u = 0; u < 48; u++) a += sx1[u] * sw[0 + u*48 + wI];
        float b = 0.f;
        #pragma unroll
        for (int u = 0; u < 10; u++) b += s_d110[u] * sw[2884 + u*48 + wI];
        orow[wI] = NORM_0E * (a * sx2[0] + RS3 * b);
    } else if (tid < 78) {
        // r1o[w,i]
        int t = tid - 48, wI = t/3, i = t%3;
        float t01 = 0.f;
        #pragma unroll 8
        for (int u = 0; u < 48; u++) t01 += sx1[u] * sw[2304 + u*10 + wI];
        float a10 = 0.f, a12 = 0.f, a211 = 0.f;
        #pragma unroll
        for (int u = 0; u < 10; u++) {
            a10  += sx1[48 + u*3 + i] * sw[2784 + u*10 + wI];
            a12  += s_c12[u*3 + i]    * sw[3464 + u*10 + wI];
            a211 += s_c211[u*3 + i]   * sw[3664 + u*10 + wI];
        }
        orow[48 + wI*3 + i] =
            NORM_1O * (RS3 * (t01 * sx2[1 + i] + sx2[0] * a10) + a12 + a211);
    } else if (tid < 108) {
        // r1e[w,k]
        int t = tid - 78, wI = t/3, k = t%3;
        float t31 = 0.f;
        #pragma unroll 8
        for (int u = 0; u < 48; u++) t31 += sx1[108 + u] * sw[6648 + u*10 + wI];
        float a112 = 0.f, a20 = 0.f, a22 = 0.f;
        #pragma unroll
        for (int u = 0; u < 10; u++) {
            a112 += s_c112[u*3 + k]   * sw[3364 + u*10 + wI];
            a20  += sx1[78 + u*3 + k] * sw[3564 + u*10 + wI];
            a22  += s_c22[u*3 + k]    * sw[4244 + u*10 + wI];
        }
        orow[78 + wI*3 + k] =
            NORM_1E * (a112 + RS3 * (sx2[0] * a20 + t31 * sx2[1 + k]) + a22);
    } else if (tid < 156) {
        // r0o[w]
        int wI = tid - 108;
        float a = 0.f;
        #pragma unroll
        for (int u = 0; u < 10; u++) a += s_d213[u] * sw[3764 + u*48 + wI];
        float b = 0.f;
        #pragma unroll 8
        for (int u = 0; u < 48; u++) b += sx1[108 + u] * sw[4344 + u*48 + wI];
        orow[108 + wI] = NORM_0O * (RS3 * a + b * sx2[0]);
    }
}

// ---------------------------------------------------------------------------
extern "C" void kernel_launch(void* const* d_in, const int* in_sizes, int n_in,
                              void* d_out, int out_size)
{
    const float* x1 = (const float*)d_in[0];
    const float* x2 = (const float*)d_in[1];
    const float* w  = (const float*)d_in[2];
    float* out = (float*)d_out;

    int B = in_sizes[1] / 9;   // x2 has 9 floats per row

    init_w3j_kernel<<<1, 128>>>();
    tp_kernel<<<B, 160>>>(x1, x2, w, out);
}

// round 3
// speedup vs baseline: 4.9830x; 1.0019x over previous
#include <cuda_runtime.h>
#include <math.h>
#include <stdint.h>

// ============================================================================
// TPForth: e3nn-style tensor product, B x (x1[156], x2[9], w[7128]) -> out[156]
// HBM-bound streaming kernel: one 320-thread block per TWO batch rows.
// Both rows' weights staged via a single contiguous 57KB cp.async.bulk,
// issued at block start (before any dependent global loads).
// ============================================================================

#define WTOT 7128
#define WBYTES (WTOT * 4)
#define XW   156

// Weight sub-matrix offsets (floats within a row), shapes (U, Wd):
//  w00  @    0 (48,48)   w01  @ 2304 (48,10)   w10  @ 2784 (10,10)
//  w110 @ 2884 (10,48)   w112 @ 3364 (10,10)   w12  @ 3464 (10,10)
//  w20  @ 3564 (10,10)   w211 @ 3664 (10,10)   w213 @ 3764 (10,48)
//  w22  @ 4244 (10,10)   w30  @ 4344 (48,48)   w31  @ 6648 (48,10)

__device__ float d_w3j111[27];   // wigner_3j(1,1,1), shape (3,3,3)
__device__ float d_w3j121[45];   // wigner_3j(1,2,1), shape (3,5,3)

// ---------------------------------------------------------------------------
// Parallel fp32 Wigner-3j init: one tensor element per thread.
// ---------------------------------------------------------------------------
struct CF { float r, i; };
__device__ __forceinline__ CF cmulf(CF a, CF b) {
    CF c; c.r = a.r*b.r - a.i*b.i; c.i = a.r*b.i + a.i*b.r; return c;
}

__device__ void change_basis_f(int l, CF* q) {  // q[(2l+1)^2], row-major
    int n = 2*l + 1;
    for (int a = 0; a < n*n; a++) { q[a].r = 0.f; q[a].i = 0.f; }
    const float rs2 = 0.70710678118654752f;
    for (int m = -l; m < 0; m++) {
        q[(l+m)*n + (l - m)].r =  rs2;
        q[(l+m)*n + (l + m)].i = -rs2;
    }
    q[l*n + l].r = 1.f;
    for (int m = 1; m <= l; m++) {
        float s = (m & 1) ? -1.f : 1.f;
        q[(l+m)*n + (l+m)].r = s * rs2;
        q[(l+m)*n + (l-m)].i = s * rs2;
    }
    CF ph;
    switch (l & 3) {  // (-i)^l
        case 0: ph.r = 1;  ph.i = 0;  break;
        case 1: ph.r = 0;  ph.i = -1; break;
        case 2: ph.r = -1; ph.i = 0;  break;
        default: ph.r = 0; ph.i = 1;  break;
    }
    for (int a = 0; a < n*n; a++) q[a] = cmulf(q[a], ph);
}

__device__ float cg_f(int j1, int j2, int j3, int m1, int m2, int m3,
                      const float* ft) {
    int vmin = -j1 + j2 + m3;
    if (-j1 + m1 > vmin) vmin = -j1 + m1;
    if (0 > vmin) vmin = 0;
    int vmax = j2 + j3 + m1;
    if (j3 - j1 + j2 < vmax) vmax = j3 - j1 + j2;
    if (j3 + m3 < vmax) vmax = j3 + m3;
    float C = sqrtf((2.f*j3 + 1.f) * ft[j3+j1-j2] * ft[j3-j1+j2] * ft[j1+j2-j3]
                    * ft[j3+m3] * ft[j3-m3]
                    / (ft[j1+j2+j3+1] * ft[j1-m1] * ft[j1+m1]
                       * ft[j2-m2] * ft[j2+m2]));
    float S = 0.f;
    for (int v = vmin; v <= vmax; v++) {
        float sgn = ((v + j2 + m2) & 1) ? -1.f : 1.f;
        S += sgn * ft[j2+j3+m1-v] * ft[j1-m1+v]
             / (ft[v] * ft[j3-j1+j2-v] * ft[j3+m3-v] * ft[v+j1-j2-m3]);
    }
    return C * S;
}

// Unnormalized element C[j,l,m] of wigner_3j(l1,l2,l3)
__device__ float w3j_elem(int l1, int l2, int l3, int j, int l, int m,
                          const float* ft) {
    int n1 = 2*l1+1, n2 = 2*l2+1, n3 = 2*l3+1;
    CF Q1[25], Q2[25], Q3[25];
    change_basis_f(l1, Q1);
    change_basis_f(l2, Q2);
    change_basis_f(l3, Q3);
    float acc = 0.f;
    for (int i = 0; i < n1; i++) {
        for (int k = 0; k < n2; k++) {
            int m3v = (i - l1) + (k - l2);
            if (m3v < -l3 || m3v > l3) continue;
            int nn = l3 + m3v;
            float cgv = cg_f(l1, l2, l3, i - l1, k - l2, m3v, ft);
            CF t = cmulf(Q1[i*n1 + j], Q2[k*n2 + l]);
            CF q3c; q3c.r = Q3[nn*n3 + m].r; q3c.i = -Q3[nn*n3 + m].i;
            t = cmulf(t, q3c);
            acc += t.r * cgv;
        }
    }
    return acc;
}

__global__ void init_w3j_kernel() {
    __shared__ float s111[27], s121[45];
    __shared__ float inv111, inv121;
    int tid = threadIdx.x;
    float ft[8];
    ft[0] = 1.f;
    for (int k = 1; k < 8; k++) ft[k] = ft[k-1] * (float)k;

    if (tid < 27) {
        int j = tid / 9, rem = tid % 9, l = rem / 3, m = rem % 3;
        s111[tid] = w3j_elem(1, 1, 1, j, l, m, ft);
    } else if (tid >= 32 && tid < 77) {
        int idx = tid - 32;
        int j = idx / 15, rem = idx % 15, l = rem / 3, m = rem % 3;
        s121[idx] = w3j_elem(1, 2, 1, j, l, m, ft);
    }
    __syncthreads();
    if (tid == 0) {
        float s = 0.f;
        for (int a = 0; a < 27; a++) s += s111[a] * s111[a];
        inv111 = rsqrtf(s);
    }
    if (tid == 1) {
        float s = 0.f;
        for (int a = 0; a < 45; a++) s += s121[a] * s121[a];
        inv121 = rsqrtf(s);
    }
    __syncthreads();
    if (tid < 27) d_w3j111[tid] = s111[tid] * inv111;
    if (tid >= 32 && tid < 77) d_w3j121[tid - 32] = s121[tid - 32] * inv121;
}

// ---------------------------------------------------------------------------
// Main kernel: one 320-thread block per TWO batch rows.
// ---------------------------------------------------------------------------
__device__ __forceinline__ uint32_t smem_u32(const void* p) {
    uint32_t a;
    asm("{ .reg .u64 t; cvta.to.shared.u64 t, %1; cvt.u32.u64 %0, t; }"
        : "=r"(a) : "l"(p));
    return a;
}

struct __align__(128) SmemLayout {
    float sw[2][WTOT];              // 57024 B, TMA destination (contiguous pair)
    float sx1[2][XW];
    float sx2[2][12];
    float d110[2][10], d213[2][10];
    float c112[2][30], c12[2][30], c211[2][30], c22[2][30];
    float sj1[27], sj2[45];
    uint64_t mbar;
};

__global__ __launch_bounds__(320) void tp_kernel(
    const float* __restrict__ x1,
    const float* __restrict__ x2,
    const float* __restrict__ w,
    float* __restrict__ out)
{
    extern __shared__ __align__(128) char smem_raw[];
    SmemLayout* S = reinterpret_cast<SmemLayout*>(smem_raw);

    const int tid  = threadIdx.x;
    const int half = tid / 160;      // which row of the pair
    const int lt   = tid - half * 160;
    const size_t z0 = (size_t)blockIdx.x * 2;

    const uint32_t mbar_a = smem_u32(&S->mbar);

    // ---- Issue the 57KB bulk copy IMMEDIATELY (tid 0, no pre-sync) ----
    if (tid == 0) {
        asm volatile("mbarrier.init.shared.b64 [%0], %1;"
                     :: "r"(mbar_a), "r"(1) : "memory");
        asm volatile("fence.proxy.async.shared::cta;" ::: "memory");
        asm volatile("mbarrier.arrive.expect_tx.shared.b64 _, [%0], %1;"
                     :: "r"(mbar_a), "r"((uint32_t)(2 * WBYTES)) : "memory");
        const float* src = w + z0 * WTOT;
        asm volatile(
            "cp.async.bulk.shared::cluster.global.mbarrier::complete_tx::bytes "
            "[%0], [%1], %2, [%3];"
            :: "r"(smem_u32(S->sw)), "l"(src), "r"((uint32_t)(2 * WBYTES)),
               "r"(mbar_a)
            : "memory");
    }

    // ---- Small operand loads (overlap the bulk copy) ----
    if (tid < 2 * (XW/4)) {                       // 78 float4 loads: both rows' x1
        int r = tid / (XW/4), o = tid % (XW/4);
        reinterpret_cast<float4*>(S->sx1[r])[o] =
            (reinterpret_cast<const float4*>(x1) + (z0 + r) * (XW/4))[o];
    } else if (tid >= 80 && tid < 98) {           // 18 floats: both rows' x2
        int r = (tid - 80) / 9, o = (tid - 80) % 9;
        S->sx2[r][o] = x2[(z0 + r) * 9 + o];
    } else if (tid >= 128 && tid < 155) {
        S->sj1[tid - 128] = d_w3j111[tid - 128];
    } else if (tid >= 160 && tid < 205) {
        S->sj2[tid - 160] = d_w3j121[tid - 160];
    }
    __syncthreads();   // sx1/sx2/sj ready; also publishes mbar init to all threads

    // ---- Aux: per-u contraction coefficients (overlap the bulk copy) ----
    {
        const float* px1 = S->sx1[half];
        const float* px2 = S->sx2[half];
        if (lt < 10) {
            float s = 0.f;
            #pragma unroll
            for (int i = 0; i < 3; i++) s += px1[48 + lt*3 + i] * px2[1 + i];
            S->d110[half][lt] = s;                       // x1_1o . x2_1o
        } else if (lt < 20) {
            int u = lt - 10; float s = 0.f;
            #pragma unroll
            for (int i = 0; i < 3; i++) s += px1[78 + u*3 + i] * px2[1 + i];
            S->d213[half][u] = s;                        // x1_1e . x2_1o
        } else if (lt < 50) {
            int t = lt - 20, u = t/3, k = t%3; float s = 0.f;
            #pragma unroll
            for (int i = 0; i < 3; i++)
                #pragma unroll
                for (int j = 0; j < 3; j++)
                    s += px1[48 + u*3 + i] * px2[1 + j] * S->sj1[i*9 + j*3 + k];
            S->c112[half][t] = s;                        // x1_1o (x) x2_1o via w3j111
        } else if (lt < 80) {
            int t = lt - 50, u = t/3, k = t%3; float s = 0.f;
            #pragma unroll
            for (int i = 0; i < 3; i++)
                #pragma unroll
                for (int j = 0; j < 5; j++)
                    s += px1[48 + u*3 + i] * px2[4 + j] * S->sj2[i*15 + j*3 + k];
            S->c12[half][t] = s;                         // x1_1o (x) x2_2e via w3j121
        } else if (lt < 110) {
            int t = lt - 80, u = t/3, k = t%3; float s = 0.f;
            #pragma unroll
            for (int i = 0; i < 3; i++)
                #pragma unroll
                for (int j = 0; j < 3; j++)
                    s += px1[78 + u*3 + i] * px2[1 + j] * S->sj1[i*9 + j*3 + k];
            S->c211[half][t] = s;                        // x1_1e (x) x2_1o via w3j111
        } else if (lt < 140) {
            int t = lt - 110, u = t/3, k = t%3; float s = 0.f;
            #pragma unroll
            for (int i = 0; i < 3; i++)
                #pragma unroll
                for (int j = 0; j < 5; j++)
                    s += px1[78 + u*3 + i] * px2[4 + j] * S->sj2[i*15 + j*3 + k];
            S->c22[half][t] = s;                         // x1_1e (x) x2_2e via w3j121
        }
    }
    __syncthreads();   // aux ready

    // ---- Wait for weights ----
    {
        uint32_t done;
        asm volatile(
            "{\n .reg .pred p;\n"
            " mbarrier.try_wait.parity.acquire.cta.shared::cta.b64 p, [%1], %2, 0x989680;\n"
            " selp.b32 %0, 1, 0, p;\n}"
            : "=r"(done) : "r"(mbar_a), "r"(0u) : "memory");
        while (!done) {
            asm volatile(
                "{\n .reg .pred p;\n"
                " mbarrier.try_wait.parity.acquire.cta.shared::cta.b64 p, [%1], %2, 0x989680;\n"
                " selp.b32 %0, 1, 0, p;\n}"
                : "=r"(done) : "r"(mbar_a), "r"(0u) : "memory");
        }
    }

    // ---- Main: one thread per output element (per half) ----
    const float NORM_0E = 0.13130643285972254f;  // sqrt(1/58)
    const float NORM_1O = 0.19611613513818404f;  // sqrt(3/78)
    const float NORM_1E = 0.19611613513818404f;  // sqrt(3/78)
    const float NORM_0O = 0.13130643285972254f;  // sqrt(1/58)
    const float RS3     = 0.57735026918962576f;  // 1/sqrt(3)

    const float* sw  = S->sw[half];
    const float* px1 = S->sx1[half];
    const float* px2 = S->sx2[half];
    float* orow = out + (z0 + half) * XW;

    if (lt < 48) {
        // r0e[w]
        int wI = lt;
        float a = 0.f;
        #pragma unroll 8
        for (int u = 0; u < 48; u++) a += px1[u] * sw[0 + u*48 + wI];
        float b = 0.f;
        #pragma unroll
        for (int u = 0; u < 10; u++) b += S->d110[half][u] * sw[2884 + u*48 + wI];
        orow[wI] = NORM_0E * (a * px2[0] + RS3 * b);
    } else if (lt < 78) {
        // r1o[w,i]
        int t = lt - 48, wI = t/3, i = t%3;
        float t01 = 0.f;
        #pragma unroll 8
        for (int u = 0; u < 48; u++) t01 += px1[u] * sw[2304 + u*10 + wI];
        float a10 = 0.f, a12 = 0.f, a211 = 0.f;
        #pragma unroll
        for (int u = 0; u < 10; u++) {
            a10  += px1[48 + u*3 + i]  * sw[2784 + u*10 + wI];
            a12  += S->c12[half][u*3 + i]  * sw[3464 + u*10 + wI];
            a211 += S->c211[half][u*3 + i] * sw[3664 + u*10 + wI];
        }
        orow[48 + wI*3 + i] =
            NORM_1O * (RS3 * (t01 * px2[1 + i] + px2[0] * a10) + a12 + a211);
    } else if (lt < 108) {
        // r1e[w,k]
        int t = lt - 78, wI = t/3, k = t%3;
        float t31 = 0.f;
        #pragma unroll 8
        for (int u = 0; u < 48; u++) t31 += px1[108 + u] * sw[6648 + u*10 + wI];
        float a112 = 0.f, a20 = 0.f, a22 = 0.f;
        #pragma unroll
        for (int u = 0; u < 10; u++) {
            a112 += S->c112[half][u*3 + k] * sw[3364 + u*10 + wI];
            a20  += px1[78 + u*3 + k]      * sw[3564 + u*10 + wI];
            a22  += S->c22[half][u*3 + k]  * sw[4244 + u*10 + wI];
        }
        orow[78 + wI*3 + k] =
            NORM_1E * (a112 + RS3 * (px2[0] * a20 + t31 * px2[1 + k]) + a22);
    } else if (lt < 156) {
        // r0o[w]
        int wI = lt - 108;
        float a = 0.f;
        #pragma unroll
        for (int u = 0; u < 10; u++) a += S->d213[half][u] * sw[3764 + u*48 + wI];
        float b = 0.f;
        #pragma unroll 8
        for (int u = 0; u < 48; u++) b += px1[108 + u] * sw[4344 + u*48 + wI];
        orow[108 + wI] = NORM_0O * (RS3 * a + b * px2[0]);
    }
}

// ---------------------------------------------------------------------------
extern "C" void kernel_launch(void* const* d_in, const int* in_sizes, int n_in,
                              void* d_out, int out_size)
{
    const float* x1 = (const float*)d_in[0];
    const float* x2 = (const float*)d_in[1];
    const float* w  = (const float*)d_in[2];
    float* out = (float*)d_out;

    int B = in_sizes[1] / 9;   // x2 has 9 floats per row
    int smem_bytes = (int)sizeof(SmemLayout);

    cudaFuncSetAttribute(tp_kernel,
                         cudaFuncAttributeMaxDynamicSharedMemorySize, smem_bytes);

    init_w3j_kernel<<<1, 128>>>();
    tp_kernel<<<B / 2, 320, smem_bytes>>>(x1, x2, w, out);
}